// round 6
// baseline (speedup 1.0000x reference)
#include <cuda_runtime.h>
#include <math.h>

#define BB 4
#define HH 8
#define LL 1024
#define DIMF 256
#define DH 32
#define SCL 0.0625f
#define NEGB (-1e30f)

typedef unsigned long long ull;
__device__ __forceinline__ void FMA2(ull &c, ull a, ull b) {
    asm("fma.rn.f32x2 %0, %1, %2, %0;" : "+l"(c) : "l"(a), "l"(b));
}
__device__ __forceinline__ float HADD2(ull v) {
    float2 f = *(float2*)&v; return f.x + f.y;
}
__device__ __forceinline__ float gelu_f(float x) {
    return 0.5f*x*(1.f + erff(x*0.70710678f));
}

__device__ float g_xq[BB*HH*LL*DH];
__device__ float g_rk[BB*HH*LL*DH];
__device__ float g_xv[BB*HH*LL*DH];
__device__ float g_rv[BB*HH*LL*DH];
__device__ float g_q [BB*HH*LL*DH];
__device__ float g_k [BB*HH*LL*DH];
__device__ float g_rm2[2*BB*HH*LL];
__device__ float g_rs2[2*BB*HH*LL];
__device__ float g_rm[BB*HH*LL];
__device__ float g_rs[BB*HH*LL];
__device__ float g_cs[BB*HH*LL];
__device__ float g_v [BB*LL*DIMF];
__device__ float g_vr[BB*LL*DIMF];

/* K1: per-head projections; zero g_cs */
__global__ void k1_proj(const float* __restrict__ x, const float* __restrict__ rx,
                        const float* __restrict__ Wq, const float* __restrict__ Wk,
                        const float* __restrict__ Wv) {
    __shared__ float wq[DH*DH], wk[DH*DH], wv[DH*DH];
    __shared__ float xr[DIMF], rr[DIMF];
    int tid = threadIdx.x, bl = blockIdx.x;
    if (bl < 128) g_cs[bl*256 + tid] = 0.f;
    for (int i = tid; i < DH*DH; i += 256) { wq[i]=Wq[i]; wk[i]=Wk[i]; wv[i]=Wv[i]; }
    xr[tid] = x[(size_t)bl*DIMF + tid];
    rr[tid] = rx[(size_t)bl*DIMF + tid];
    __syncthreads();
    int h = tid>>5, d = tid&31;
    float aq=0.f, av=0.f, ak=0.f, ar=0.f;
#pragma unroll
    for (int j=0;j<DH;j++) {
        float xv_ = xr[h*DH+j], rv_ = rr[h*DH+j];
        aq += xv_*wq[j*DH+d]; av += xv_*wv[j*DH+d];
        ak += rv_*wk[j*DH+d]; ar += rv_*wv[j*DH+d];
    }
    int b = bl>>10, l = bl&1023;
    size_t o = (((size_t)b*HH + h)*LL + l)*DH + d;
    g_xq[o]=aq; g_xv[o]=av; g_rk[o]=ak; g_rv[o]=ar;
}

/* K2s: sparse aggregation (adj entries exactly {0,1}). Warp per 4 rows,
   t-tile outer so the 4 gather chains interleave; dual-pop for MLP=2. */
__global__ void k2s_agg(const float* __restrict__ adj, const float* __restrict__ adjr) {
    int tid = threadIdx.x, w = tid>>5, lane = tid&31;
    int bh = blockIdx.y;
    const float* A = blockIdx.z ? adjr : adj;
    const float* X = blockIdx.z ? g_rk : g_xq;
    float*       O = blockIdx.z ? g_k  : g_q;
    const float* Ab = A + (size_t)bh*LL*LL;
    const float* Xb = X + (size_t)bh*LL*DH;
    float*       Ob = O + (size_t)bh*LL*DH;
    int lbase = blockIdx.x*32 + w*4;
    float acc[4] = {0.f,0.f,0.f,0.f};
    for (int t0=0; t0<LL; t0+=32) {
        unsigned mask[4];
#pragma unroll
        for (int r=0;r<4;r++) {
            float av = Ab[(size_t)(lbase+r)*LL + t0 + lane];
            mask[r] = __ballot_sync(0xffffffffu, av > 0.f);
        }
#pragma unroll
        for (int r=0;r<4;r++) {
            unsigned m = mask[r];
            while (m) {
                int b0 = __ffs(m)-1; m &= m-1;
                float v0 = Xb[(size_t)(t0+b0)*DH + lane];
                if (m) {
                    int b1 = __ffs(m)-1; m &= m-1;
                    float v1 = Xb[(size_t)(t0+b1)*DH + lane];
                    acc[r] += v0; acc[r] += v1;
                } else acc[r] += v0;
            }
        }
    }
#pragma unroll
    for (int r=0;r<4;r++) Ob[(size_t)(lbase+r)*DH + lane] = acc[r];
}

/* K34: fused logits + leaky + R-mix + mask + online row stats.
   phase1 uses packed f32x2 FMAs on float4 reg-pairs. */
__global__ void k34_fused(const float* __restrict__ adj, const float* __restrict__ R,
                          float* __restrict__ Ab) {
    extern __shared__ float sm[];
    float* qs = sm;            /* [8][16][36] */
    float* ks = sm + 4608;     /* [8][32][36] */
    float* Ss = sm + 13824;    /* [8][16][36] */
    int tid = threadIdx.x, b = blockIdx.y, l0 = blockIdx.x*16;
    int w = tid>>5, lane = tid&31;
    int lg = lane>>3, tg = lane&7;
    float Rr[8];
#pragma unroll
    for (int h=0;h<8;h++) Rr[h] = R[w*8+h];
#pragma unroll
    for (int i=0;i<4;i++) {
        int e = tid + i*256;
        int h = e>>7, rem = e&127, l = rem>>3, d4 = (rem&7)*4;
        *(float4*)&qs[(h*16+l)*36+d4] =
            *(const float4*)(g_q + (((size_t)b*HH+h)*LL + l0+l)*DH + d4);
    }
    float m16[16], s16[16];
#pragma unroll
    for (int l=0;l<16;l++){ m16[l]=NEGB; s16[l]=0.f; }
    int tbeg = blockIdx.z*512, tend = tbeg+512;
    for (int t0=tbeg; t0<tend; t0+=32) {
        __syncthreads();
#pragma unroll
        for (int i=0;i<8;i++) {
            int e = tid + i*256;
            int h = e>>8, rem = e&255, tt = rem>>3, d4 = (rem&7)*4;
            *(float4*)&ks[(h*32+tt)*36+d4] =
                *(const float4*)(g_k + (((size_t)b*HH+h)*LL + t0+tt)*DH + d4);
        }
        __syncthreads();
        {
            ull s2[4][4];
#pragma unroll
            for (int i=0;i<4;i++)
#pragma unroll
                for (int j=0;j<4;j++) s2[i][j] = 0ULL;
#pragma unroll
            for (int dq=0; dq<8; dq++) {
                ulonglong2 qp[4], kp[4];
#pragma unroll
                for (int i=0;i<4;i++)
                    qp[i] = *(const ulonglong2*)&qs[(w*16+lg+4*i)*36+dq*4];
#pragma unroll
                for (int j=0;j<4;j++)
                    kp[j] = *(const ulonglong2*)&ks[(w*32+tg+8*j)*36+dq*4];
#pragma unroll
                for (int i=0;i<4;i++)
#pragma unroll
                    for (int j=0;j<4;j++) {
                        FMA2(s2[i][j], qp[i].x, kp[j].x);
                        FMA2(s2[i][j], qp[i].y, kp[j].y);
                    }
            }
#pragma unroll
            for (int i=0;i<4;i++)
#pragma unroll
                for (int j=0;j<4;j++) {
                    float v = HADD2(s2[i][j])*SCL;
                    Ss[(w*16+lg+4*i)*36+tg+8*j] = v>0.f ? v : 0.01f*v;
                }
        }
        __syncthreads();
#pragma unroll
        for (int l=0;l<16;l++) {
            float z = 0.f;
#pragma unroll
            for (int h=0;h<8;h++) z += Rr[h]*Ss[(h*16+l)*36 + lane];
            size_t gi = (((size_t)b*HH+w)*LL + l0+l)*LL + t0 + lane;
            if (!(adj[gi] > 0.f)) z = NEGB;
            Ab[gi] = z;
            float mo = m16[l];
            if (z > mo) { s16[l] = s16[l]*__expf(mo - z) + 1.f; m16[l] = z; }
            else s16[l] += __expf(z - mo);
        }
    }
#pragma unroll
    for (int l=0;l<16;l++) {
        float m = m16[l], s = s16[l];
#pragma unroll
        for (int o=16;o;o>>=1) {
            float mo = __shfl_xor_sync(0xffffffffu, m, o);
            float so = __shfl_xor_sync(0xffffffffu, s, o);
            float mn = fmaxf(m, mo);
            s = s*__expf(m-mn) + so*__expf(mo-mn);
            m = mn;
        }
        if (lane == 0) {
            size_t ridx = ((size_t)b*HH+w)*LL + l0+l;
            g_rm2[(size_t)blockIdx.z*32768 + ridx] = m;
            g_rs2[(size_t)blockIdx.z*32768 + ridx] = s;
        }
    }
}

/* K5m: merge the two t-half softmax stats per row. */
__global__ void k5_merge() {
    int i = blockIdx.x*256 + threadIdx.x;
    float m1 = g_rm2[i], m2 = g_rm2[32768+i];
    float s1 = g_rs2[i], s2 = g_rs2[32768+i];
    float m = fmaxf(m1, m2);
    float s = s1*__expf(m1-m) + s2*__expf(m2-m);
    g_rm[i] = m; g_rs[i] = s;
}

/* K6: A = exp(z-m)/s in place; colsum += sum_l exp(A); v = gelu(A @ xv).
   f32x2 inner: pair over t; xv tile stored transposed [d][t]. */
__global__ void k6_norm_v(float* __restrict__ Ab) {
    __shared__ float Ps[64][36];
    __shared__ float xt[32][34];
    __shared__ float csum[LL];
    __shared__ float rm[64], ri[64];
    int tid = threadIdx.x, bh = blockIdx.y;
    int l0 = blockIdx.x * 64;
    if (tid < 64) {
        rm[tid] = g_rm[(size_t)bh*LL + l0+tid];
        ri[tid] = 1.f / g_rs[(size_t)bh*LL + l0+tid];
    }
#pragma unroll
    for (int i=0;i<8;i++) csum[tid+i*128] = 0.f;
    int lq = tid>>3, dg = tid&7;
    ull acc2[4][4];
#pragma unroll
    for (int i=0;i<4;i++)
#pragma unroll
        for (int c=0;c<4;c++) acc2[i][c] = 0ULL;
    __syncthreads();
    for (int t0=0; t0<LL; t0+=32) {
#pragma unroll
        for (int i=0;i<4;i++) {
            int e = tid + i*128, l = e>>3, t4 = (e&7)*4;
            float4 z = *(const float4*)(Ab + ((size_t)bh*LL + l0+l)*LL + t0 + t4);
            float m = rm[l], s = ri[l];
            float4 p;
            p.x = __expf(z.x-m)*s; p.y = __expf(z.y-m)*s;
            p.z = __expf(z.z-m)*s; p.w = __expf(z.w-m)*s;
            *(float4*)&Ps[l][t4] = p;
            *(float4*)(Ab + ((size_t)bh*LL + l0+l)*LL + t0 + t4) = p;
        }
#pragma unroll
        for (int i=0;i<2;i++) {
            int e = tid + i*128, t = e>>3, d4 = (e&7)*4;
            float4 v = *(const float4*)(g_xv + ((size_t)bh*LL + t0+t)*DH + d4);
            xt[d4  ][t] = v.x; xt[d4+1][t] = v.y;
            xt[d4+2][t] = v.z; xt[d4+3][t] = v.w;
        }
        __syncthreads();
        {
            int w = tid>>5, t = tid&31;
            float s = 0.f;
#pragma unroll
            for (int r=0;r<16;r++) s += __expf(Ps[w*16+r][t]);
            atomicAdd(&csum[t0+t], s);
        }
#pragma unroll
        for (int tp=0; tp<16; tp++) {
            ull p2[4], x2[4];
#pragma unroll
            for (int i=0;i<4;i++) p2[i] = *(const ull*)&Ps[lq+16*i][2*tp];
#pragma unroll
            for (int c=0;c<4;c++) x2[c] = *(const ull*)&xt[dg*4+c][2*tp];
#pragma unroll
            for (int i=0;i<4;i++)
#pragma unroll
                for (int c=0;c<4;c++) FMA2(acc2[i][c], p2[i], x2[c]);
        }
        __syncthreads();
    }
    int b = bh>>3, h = bh&7;
#pragma unroll
    for (int i=0;i<4;i++) {
        float4 o;
        o.x = gelu_f(HADD2(acc2[i][0])); o.y = gelu_f(HADD2(acc2[i][1]));
        o.z = gelu_f(HADD2(acc2[i][2])); o.w = gelu_f(HADD2(acc2[i][3]));
        *(float4*)(g_v + (size_t)(b*LL + l0+lq+16*i)*DIMF + h*DH + dg*4) = o;
    }
#pragma unroll
    for (int i=0;i<8;i++)
        atomicAdd(&g_cs[(size_t)bh*LL + tid + i*128], csum[tid+i*128]);
}

/* K7: Ar[t,l] = exp(A[l,t])/colsum[t]; vr = gelu(Ar @ rv). f32x2 pair over l. */
__global__ void k7_ar_vr(const float* __restrict__ Ab, float* __restrict__ Ar) {
    __shared__ float Es[64][36];
    __shared__ float rt_[32][34];
    __shared__ float ci[64];
    int tid = threadIdx.x, bh = blockIdx.y;
    int t0 = blockIdx.x * 64;
    if (tid < 64) ci[tid] = 1.f / g_cs[(size_t)bh*LL + t0 + tid];
    int tq = tid>>3, dg = tid&7;
    ull acc2[4][4];
#pragma unroll
    for (int i=0;i<4;i++)
#pragma unroll
        for (int c=0;c<4;c++) acc2[i][c] = 0ULL;
    __syncthreads();
    for (int l0=0; l0<LL; l0+=32) {
#pragma unroll
        for (int i=0;i<4;i++) {
            int e = tid + i*128;
            int l = (e>>3)&31, t4 = (e&7)*4 + ((e>>8)<<5);
            float4 a = *(const float4*)(Ab + ((size_t)bh*LL + l0+l)*LL + t0 + t4);
            Es[t4  ][l] = __expf(a.x)*ci[t4];
            Es[t4+1][l] = __expf(a.y)*ci[t4+1];
            Es[t4+2][l] = __expf(a.z)*ci[t4+2];
            Es[t4+3][l] = __expf(a.w)*ci[t4+3];
        }
#pragma unroll
        for (int i=0;i<2;i++) {
            int e = tid + i*128, l = e>>3, d4 = (e&7)*4;
            float4 v = *(const float4*)(g_rv + ((size_t)bh*LL + l0+l)*DH + d4);
            rt_[d4  ][l] = v.x; rt_[d4+1][l] = v.y;
            rt_[d4+2][l] = v.z; rt_[d4+3][l] = v.w;
        }
        __syncthreads();
#pragma unroll
        for (int i=0;i<4;i++) {
            int e = tid + i*128, t = e>>3, l4 = (e&7)*4;
            *(float4*)(Ar + ((size_t)bh*LL + t0+t)*LL + l0 + l4) = *(float4*)&Es[t][l4];
        }
#pragma unroll
        for (int lp=0; lp<16; lp++) {
            ull e2[4], r2[4];
#pragma unroll
            for (int i=0;i<4;i++) e2[i] = *(const ull*)&Es[tq+16*i][2*lp];
#pragma unroll
            for (int c=0;c<4;c++) r2[c] = *(const ull*)&rt_[dg*4+c][2*lp];
#pragma unroll
            for (int i=0;i<4;i++)
#pragma unroll
                for (int c=0;c<4;c++) FMA2(acc2[i][c], e2[i], r2[c]);
        }
        __syncthreads();
    }
    int b = bh>>3, h = bh&7;
#pragma unroll
    for (int i=0;i<4;i++) {
        float4 o;
        o.x = gelu_f(HADD2(acc2[i][0])); o.y = gelu_f(HADD2(acc2[i][1]));
        o.z = gelu_f(HADD2(acc2[i][2])); o.w = gelu_f(HADD2(acc2[i][3]));
        *(float4*)(g_vr + (size_t)(b*LL + t0+tq+16*i)*DIMF + h*DH + dg*4) = o;
    }
}

/* K8: out = gv @ Wp (gelu pre-applied). f32x2 pair over k; Ws transposed. */
__global__ void k8_out(const float* __restrict__ Wp, float* __restrict__ out,
                       float* __restrict__ outr) {
    __shared__ float Vs[64][36];
    __shared__ float WsT[64][34];
    int tid = threadIdx.x;
    const float* V = blockIdx.z ? g_vr : g_v;
    float* O = blockIdx.z ? outr : out;
    int r0 = blockIdx.x*64, n0 = blockIdx.y*64;
    int rg = tid>>4, ng = tid&15;
    ull acc2[4][4];
#pragma unroll
    for (int i=0;i<4;i++)
#pragma unroll
        for (int c=0;c<4;c++) acc2[i][c] = 0ULL;
    for (int k0=0; k0<DIMF; k0+=32) {
#pragma unroll
        for (int it=0; it<2; it++) {
            int e = tid + it*256;
            int r = e>>3, k4 = (e&7)*4;
            *(float4*)&Vs[r][k4] = *(const float4*)(V + (size_t)(r0+r)*DIMF + k0 + k4);
            int kk = e>>4, n4 = (e&15)*4;
            float4 wv = *(const float4*)(Wp + (size_t)(k0+kk)*DIMF + n0 + n4);
            WsT[n4  ][kk] = wv.x; WsT[n4+1][kk] = wv.y;
            WsT[n4+2][kk] = wv.z; WsT[n4+3][kk] = wv.w;
        }
        __syncthreads();
#pragma unroll
        for (int kp=0; kp<16; kp++) {
            ull v2[4], w2[4];
#pragma unroll
            for (int i=0;i<4;i++) v2[i] = *(const ull*)&Vs[rg+16*i][2*kp];
#pragma unroll
            for (int c=0;c<4;c++) w2[c] = *(const ull*)&WsT[ng*4+c][2*kp];
#pragma unroll
            for (int i=0;i<4;i++)
#pragma unroll
                for (int c=0;c<4;c++) FMA2(acc2[i][c], v2[i], w2[c]);
        }
        __syncthreads();
    }
#pragma unroll
    for (int i=0;i<4;i++) {
        float4 o;
        o.x = HADD2(acc2[i][0]); o.y = HADD2(acc2[i][1]);
        o.z = HADD2(acc2[i][2]); o.w = HADD2(acc2[i][3]);
        *(float4*)(O + (size_t)(r0+rg+16*i)*DIMF + n0 + ng*4) = o;
    }
}

extern "C" void kernel_launch(void* const* d_in, const int* in_sizes, int n_in,
                              void* d_out, int out_size) {
    const float* x    = (const float*)d_in[0];
    const float* rx   = (const float*)d_in[1];
    const float* adj  = (const float*)d_in[2];
    const float* adjr = (const float*)d_in[3];
    const float* Wq   = (const float*)d_in[4];
    const float* Wk   = (const float*)d_in[5];
    const float* Wv   = (const float*)d_in[6];
    const float* R    = (const float*)d_in[7];
    const float* Wp   = (const float*)d_in[8];
    float* out  = (float*)d_out;
    float* outr = out + 1048576;
    float* Ab   = out + 2097152;
    float* Arb  = Ab + 33554432;
    static int smset = 0;
    if (!smset) {
        cudaFuncSetAttribute(k34_fused, cudaFuncAttributeMaxDynamicSharedMemorySize, 73728);
        smset = 1;
    }
    k1_proj<<<4096, 256>>>(x, rx, Wq, Wk, Wv);
    k2s_agg<<<dim3(32,32,2), 256>>>(adj, adjr);
    k34_fused<<<dim3(64,4,2), 256, 73728>>>(adj, R, Ab);
    k5_merge<<<128, 256>>>();
    k6_norm_v<<<dim3(16,32), 128>>>(Ab);
    k7_ar_vr<<<dim3(16,32), 128>>>(Ab, Arb);
    k8_out<<<dim3(64,4,2), 256>>>(Wp, out, outr);
}

// round 7
// speedup vs baseline: 1.2649x; 1.2649x over previous
#include <cuda_runtime.h>
#include <math.h>

#define BB 4
#define HH 8
#define LL 1024
#define DIMF 256
#define DH 32
#define SCL 0.0625f
#define NEGB (-1e30f)
#define VSLC (BB*LL*DIMF)

__device__ float g_xq[BB*HH*LL*DH];
__device__ float g_rk[BB*HH*LL*DH];
__device__ float g_xv[BB*HH*LL*DH];
__device__ float g_rv[BB*HH*LL*DH];
__device__ float g_q [BB*HH*LL*DH];
__device__ float g_k [BB*HH*LL*DH];
__device__ unsigned g_msk[BB*HH*LL*32];
__device__ float g_rm2[2*BB*HH*LL];
__device__ float g_rs2[2*BB*HH*LL];
__device__ float g_rm[BB*HH*LL];
__device__ float g_rs[BB*HH*LL];
__device__ float g_cs[BB*HH*LL];
__device__ float g_v4 [4*VSLC];
__device__ float g_vr4[4*VSLC];

/* K1: per-head projections; zero g_cs */
__global__ void k1_proj(const float* __restrict__ x, const float* __restrict__ rx,
                        const float* __restrict__ Wq, const float* __restrict__ Wk,
                        const float* __restrict__ Wv) {
    __shared__ float wq[DH*DH], wk[DH*DH], wv[DH*DH];
    __shared__ float xr[DIMF], rr[DIMF];
    int tid = threadIdx.x, bl = blockIdx.x;
    if (bl < 128) g_cs[bl*256 + tid] = 0.f;
    for (int i = tid; i < DH*DH; i += 256) { wq[i]=Wq[i]; wk[i]=Wk[i]; wv[i]=Wv[i]; }
    xr[tid] = x[(size_t)bl*DIMF + tid];
    rr[tid] = rx[(size_t)bl*DIMF + tid];
    __syncthreads();
    int h = tid>>5, d = tid&31;
    float aq=0.f, av=0.f, ak=0.f, ar=0.f;
#pragma unroll
    for (int j=0;j<DH;j++) {
        float xv_ = xr[h*DH+j], rv_ = rr[h*DH+j];
        aq += xv_*wq[j*DH+d]; av += xv_*wv[j*DH+d];
        ak += rv_*wk[j*DH+d]; ar += rv_*wv[j*DH+d];
    }
    int b = bl>>10, l = bl&1023;
    size_t o = (((size_t)b*HH + h)*LL + l)*DH + d;
    g_xq[o]=aq; g_xv[o]=av; g_rk[o]=ak; g_rv[o]=ar;
}

/* K2s: sparse aggregation (adj entries exactly {0,1}); also stores the adj
   bitmask words (z==0) so k34 never has to re-read the 128MB adj tensor. */
__global__ void k2s_agg(const float* __restrict__ adj, const float* __restrict__ adjr) {
    int tid = threadIdx.x, w = tid>>5, lane = tid&31;
    int bh = blockIdx.y;
    const float* A = blockIdx.z ? adjr : adj;
    const float* X = blockIdx.z ? g_rk : g_xq;
    float*       O = blockIdx.z ? g_k  : g_q;
    const float* Ab = A + (size_t)bh*LL*LL;
    const float* Xb = X + (size_t)bh*LL*DH;
    float*       Ob = O + (size_t)bh*LL*DH;
    int lbase = blockIdx.x*32 + w*4;
    float acc[4] = {0.f,0.f,0.f,0.f};
    for (int t0=0; t0<LL; t0+=32) {
        unsigned mask[4];
#pragma unroll
        for (int r=0;r<4;r++) {
            float av = Ab[(size_t)(lbase+r)*LL + t0 + lane];
            mask[r] = __ballot_sync(0xffffffffu, av > 0.f);
        }
        if (blockIdx.z == 0) {
#pragma unroll
            for (int r=0;r<4;r++)
                if (lane == r)
                    g_msk[((size_t)bh*LL + lbase+r)*32 + (t0>>5)] = mask[r];
        }
#pragma unroll
        for (int r=0;r<4;r++) {
            unsigned m = mask[r];
            while (m) {
                int b0 = __ffs(m)-1; m &= m-1;
                float v0 = Xb[(size_t)(t0+b0)*DH + lane];
                if (m) {
                    int b1 = __ffs(m)-1; m &= m-1;
                    float v1 = Xb[(size_t)(t0+b1)*DH + lane];
                    acc[r] += v0; acc[r] += v1;
                } else acc[r] += v0;
            }
        }
    }
#pragma unroll
    for (int r=0;r<4;r++) Ob[(size_t)(lbase+r)*DH + lane] = acc[r];
}

/* K34: fused logits + leaky + R-mix + bitmask + online row stats. */
__global__ void k34_fused(const float* __restrict__ R, float* __restrict__ Ab) {
    extern __shared__ float sm[];
    float* qs = sm;            /* [8][16][36] */
    float* ks = sm + 4608;     /* [8][32][36] */
    float* Ss = sm + 13824;    /* [8][16][36] */
    int tid = threadIdx.x, b = blockIdx.y, l0 = blockIdx.x*16;
    int w = tid>>5, lane = tid&31;
    int lg = lane>>3, tg = lane&7;
    float Rr[8];
#pragma unroll
    for (int h=0;h<8;h++) Rr[h] = R[w*8+h];
#pragma unroll
    for (int i=0;i<4;i++) {
        int e = tid + i*256;
        int h = e>>7, rem = e&127, l = rem>>3, d4 = (rem&7)*4;
        *(float4*)&qs[(h*16+l)*36+d4] =
            *(const float4*)(g_q + (((size_t)b*HH+h)*LL + l0+l)*DH + d4);
    }
    float m16[16], s16[16];
#pragma unroll
    for (int l=0;l<16;l++){ m16[l]=NEGB; s16[l]=0.f; }
    int tbeg = blockIdx.z*512, tend = tbeg+512;
    for (int t0=tbeg; t0<tend; t0+=32) {
        __syncthreads();
#pragma unroll
        for (int i=0;i<8;i++) {
            int e = tid + i*256;
            int h = e>>8, rem = e&255, tt = rem>>3, d4 = (rem&7)*4;
            *(float4*)&ks[(h*32+tt)*36+d4] =
                *(const float4*)(g_k + (((size_t)b*HH+h)*LL + t0+tt)*DH + d4);
        }
        __syncthreads();
        {
            float s[4][4];
#pragma unroll
            for (int i=0;i<4;i++)
#pragma unroll
                for (int j=0;j<4;j++) s[i][j]=0.f;
#pragma unroll
            for (int dq=0; dq<8; dq++) {
                float4 q4[4], k4[4];
#pragma unroll
                for (int i=0;i<4;i++) q4[i] = *(const float4*)&qs[(w*16+lg+4*i)*36+dq*4];
#pragma unroll
                for (int j=0;j<4;j++) k4[j] = *(const float4*)&ks[(w*32+tg+8*j)*36+dq*4];
#pragma unroll
                for (int i=0;i<4;i++)
#pragma unroll
                    for (int j=0;j<4;j++)
                        s[i][j] += q4[i].x*k4[j].x + q4[i].y*k4[j].y
                                 + q4[i].z*k4[j].z + q4[i].w*k4[j].w;
            }
#pragma unroll
            for (int i=0;i<4;i++)
#pragma unroll
                for (int j=0;j<4;j++) {
                    float v = s[i][j]*SCL;
                    Ss[(w*16+lg+4*i)*36+tg+8*j] = v>0.f ? v : 0.01f*v;
                }
        }
        __syncthreads();
#pragma unroll
        for (int l=0;l<16;l++) {
            float z = 0.f;
#pragma unroll
            for (int h=0;h<8;h++) z += Rr[h]*Ss[(h*16+l)*36 + lane];
            size_t row = ((size_t)b*HH+w)*LL + l0+l;
            unsigned mw = g_msk[row*32 + (t0>>5)];
            if (!((mw >> lane) & 1u)) z = NEGB;
            Ab[row*LL + t0 + lane] = z;
            float mo = m16[l];
            if (z > mo) { s16[l] = s16[l]*__expf(mo - z) + 1.f; m16[l] = z; }
            else s16[l] += __expf(z - mo);
        }
    }
#pragma unroll
    for (int l=0;l<16;l++) {
        float m = m16[l], s = s16[l];
#pragma unroll
        for (int o=16;o;o>>=1) {
            float mo = __shfl_xor_sync(0xffffffffu, m, o);
            float so = __shfl_xor_sync(0xffffffffu, s, o);
            float mn = fmaxf(m, mo);
            s = s*__expf(m-mn) + so*__expf(mo-mn);
            m = mn;
        }
        if (lane == 0) {
            size_t ridx = ((size_t)b*HH+w)*LL + l0+l;
            g_rm2[(size_t)blockIdx.z*32768 + ridx] = m;
            g_rs2[(size_t)blockIdx.z*32768 + ridx] = s;
        }
    }
}

/* K5m: merge the two t-half softmax stats per row. */
__global__ void k5_merge() {
    int i = blockIdx.x*256 + threadIdx.x;
    float m1 = g_rm2[i], m2 = g_rm2[32768+i];
    float s1 = g_rs2[i], s2 = g_rs2[32768+i];
    float m = fmaxf(m1, m2);
    float s = s1*__expf(m1-m) + s2*__expf(m2-m);
    g_rm[i] = m; g_rs[i] = s;
}

/* K6: A = exp(z-m)/s in place; colsum += sum_l exp(A); v partial = A @ xv.
   blockIdx.z = t-chunk of 256 (4 chunks -> 4x grid for latency hiding). */
__global__ void k6_norm_v(float* __restrict__ Ab) {
    __shared__ float Ps[64][36], xs[32][36], csum[256];
    __shared__ float rm[64], ri[64];
    int tid = threadIdx.x, bh = blockIdx.y;
    int l0 = blockIdx.x * 64, tz = blockIdx.z*256;
    if (tid < 64) {
        rm[tid] = g_rm[(size_t)bh*LL + l0+tid];
        ri[tid] = 1.f / g_rs[(size_t)bh*LL + l0+tid];
    }
    csum[tid] = 0.f; csum[tid+128] = 0.f;
    int lq = tid>>3, dg = tid&7;
    float4 acc[4];
#pragma unroll
    for (int i=0;i<4;i++) acc[i] = make_float4(0.f,0.f,0.f,0.f);
    __syncthreads();
    for (int t0=tz; t0<tz+256; t0+=32) {
#pragma unroll
        for (int i=0;i<4;i++) {
            int e = tid + i*128, l = e>>3, t4 = (e&7)*4;
            float4 z = *(const float4*)(Ab + ((size_t)bh*LL + l0+l)*LL + t0 + t4);
            float m = rm[l], s = ri[l];
            float4 p;
            p.x = __expf(z.x-m)*s; p.y = __expf(z.y-m)*s;
            p.z = __expf(z.z-m)*s; p.w = __expf(z.w-m)*s;
            *(float4*)&Ps[l][t4] = p;
            *(float4*)(Ab + ((size_t)bh*LL + l0+l)*LL + t0 + t4) = p;
        }
#pragma unroll
        for (int i=0;i<2;i++) {
            int e = tid + i*128, l = e>>3, d4 = (e&7)*4;
            *(float4*)&xs[l][d4] = *(const float4*)(g_xv + ((size_t)bh*LL + t0+l)*DH + d4);
        }
        __syncthreads();
        {
            int w = tid>>5, t = tid&31;
            float s = 0.f;
#pragma unroll
            for (int r=0;r<16;r++) s += __expf(Ps[w*16+r][t]);
            atomicAdd(&csum[t0-tz+t], s);
        }
#pragma unroll
        for (int tt=0; tt<32; tt++) {
            float4 x4 = *(const float4*)&xs[tt][dg*4];
#pragma unroll
            for (int i=0;i<4;i++) {
                float p = Ps[lq+16*i][tt];
                acc[i].x += p*x4.x; acc[i].y += p*x4.y;
                acc[i].z += p*x4.z; acc[i].w += p*x4.w;
            }
        }
        __syncthreads();
    }
    int b = bh>>3, h = bh&7;
#pragma unroll
    for (int i=0;i<4;i++)
        *(float4*)(g_v4 + (size_t)blockIdx.z*VSLC
                   + (size_t)(b*LL + l0+lq+16*i)*DIMF + h*DH + dg*4) = acc[i];
    atomicAdd(&g_cs[(size_t)bh*LL + tz + tid],       csum[tid]);
    atomicAdd(&g_cs[(size_t)bh*LL + tz + tid + 128], csum[tid+128]);
}

/* K7: Ar[t,l] = exp(A[l,t])/colsum[t] (transposed write); vr partial = Ar @ rv.
   blockIdx.z = l-chunk of 256. */
__global__ void k7_ar_vr(const float* __restrict__ Ab, float* __restrict__ Ar) {
    __shared__ float Es[64][36], rs_[32][36], ci[64];
    int tid = threadIdx.x, bh = blockIdx.y;
    int t0 = blockIdx.x * 64, lz = blockIdx.z*256;
    if (tid < 64) ci[tid] = 1.f / g_cs[(size_t)bh*LL + t0 + tid];
    int tq = tid>>3, dg = tid&7;
    float4 acc[4];
#pragma unroll
    for (int i=0;i<4;i++) acc[i] = make_float4(0.f,0.f,0.f,0.f);
    __syncthreads();
    for (int l0=lz; l0<lz+256; l0+=32) {
#pragma unroll
        for (int i=0;i<4;i++) {
            int e = tid + i*128;
            int l = (e>>3)&31, t4 = (e&7)*4 + ((e>>8)<<5);
            float4 a = *(const float4*)(Ab + ((size_t)bh*LL + l0+l)*LL + t0 + t4);
            Es[t4  ][l] = __expf(a.x)*ci[t4];
            Es[t4+1][l] = __expf(a.y)*ci[t4+1];
            Es[t4+2][l] = __expf(a.z)*ci[t4+2];
            Es[t4+3][l] = __expf(a.w)*ci[t4+3];
        }
#pragma unroll
        for (int i=0;i<2;i++) {
            int e = tid + i*128, l = e>>3, d4 = (e&7)*4;
            *(float4*)&rs_[l][d4] = *(const float4*)(g_rv + ((size_t)bh*LL + l0+l)*DH + d4);
        }
        __syncthreads();
#pragma unroll
        for (int i=0;i<4;i++) {
            int e = tid + i*128, t = e>>3, l4 = (e&7)*4;
            *(float4*)(Ar + ((size_t)bh*LL + t0+t)*LL + l0 + l4) = *(float4*)&Es[t][l4];
        }
#pragma unroll
        for (int ll=0; ll<32; ll++) {
            float4 r4 = *(const float4*)&rs_[ll][dg*4];
#pragma unroll
            for (int i=0;i<4;i++) {
                float e_ = Es[tq+16*i][ll];
                acc[i].x += e_*r4.x; acc[i].y += e_*r4.y;
                acc[i].z += e_*r4.z; acc[i].w += e_*r4.w;
            }
        }
        __syncthreads();
    }
    int b = bh>>3, h = bh&7;
#pragma unroll
    for (int i=0;i<4;i++)
        *(float4*)(g_vr4 + (size_t)blockIdx.z*VSLC
                   + (size_t)(b*LL + t0+tq+16*i)*DIMF + h*DH + dg*4) = acc[i];
}

/* K8: sum 4 partial v slices, gelu, @ Wp. */
__global__ void k8_out(const float* __restrict__ Wp, float* __restrict__ out,
                       float* __restrict__ outr) {
    __shared__ float Vs[64][36], Ws[32][68];
    int tid = threadIdx.x;
    const float* V = blockIdx.z ? g_vr4 : g_v4;
    float* O = blockIdx.z ? outr : out;
    int r0 = blockIdx.x*64, n0 = blockIdx.y*64;
    int rg = tid>>4, ng = tid&15;
    float4 acc[4];
#pragma unroll
    for (int i=0;i<4;i++) acc[i] = make_float4(0.f,0.f,0.f,0.f);
    for (int k0=0; k0<DIMF; k0+=32) {
#pragma unroll
        for (int it=0; it<2; it++) {
            int e = tid + it*256;
            int r = e>>3, k4 = (e&7)*4;
            size_t off = (size_t)(r0+r)*DIMF + k0 + k4;
            float4 v0 = *(const float4*)(V + off);
            float4 v1 = *(const float4*)(V + VSLC + off);
            float4 v2 = *(const float4*)(V + 2*(size_t)VSLC + off);
            float4 v3 = *(const float4*)(V + 3*(size_t)VSLC + off);
            float4 v;
            v.x = v0.x+v1.x+v2.x+v3.x; v.y = v0.y+v1.y+v2.y+v3.y;
            v.z = v0.z+v1.z+v2.z+v3.z; v.w = v0.w+v1.w+v2.w+v3.w;
            float* pv = (float*)&v;
#pragma unroll
            for (int j=0;j<4;j++){ float xx = pv[j]; pv[j] = 0.5f*xx*(1.f+erff(xx*0.70710678f)); }
            *(float4*)&Vs[r][k4] = v;
            int kk = e>>4, n4 = (e&15)*4;
            *(float4*)&Ws[kk][n4] = *(const float4*)(Wp + (size_t)(k0+kk)*DIMF + n0 + n4);
        }
        __syncthreads();
#pragma unroll
        for (int k=0;k<32;k++) {
            float4 w4 = *(const float4*)&Ws[k][ng*4];
#pragma unroll
            for (int i=0;i<4;i++) {
                float vv = Vs[rg+16*i][k];
                acc[i].x += vv*w4.x; acc[i].y += vv*w4.y;
                acc[i].z += vv*w4.z; acc[i].w += vv*w4.w;
            }
        }
        __syncthreads();
    }
#pragma unroll
    for (int i=0;i<4;i++)
        *(float4*)(O + (size_t)(r0+rg+16*i)*DIMF + n0 + ng*4) = acc[i];
}

extern "C" void kernel_launch(void* const* d_in, const int* in_sizes, int n_in,
                              void* d_out, int out_size) {
    const float* x    = (const float*)d_in[0];
    const float* rx   = (const float*)d_in[1];
    const float* adj  = (const float*)d_in[2];
    const float* adjr = (const float*)d_in[3];
    const float* Wq   = (const float*)d_in[4];
    const float* Wk   = (const float*)d_in[5];
    const float* Wv   = (const float*)d_in[6];
    const float* R    = (const float*)d_in[7];
    const float* Wp   = (const float*)d_in[8];
    float* out  = (float*)d_out;
    float* outr = out + 1048576;
    float* Ab   = out + 2097152;
    float* Arb  = Ab + 33554432;
    static int smset = 0;
    if (!smset) {
        cudaFuncSetAttribute(k34_fused, cudaFuncAttributeMaxDynamicSharedMemorySize, 73728);
        smset = 1;
    }
    k1_proj<<<4096, 256>>>(x, rx, Wq, Wk, Wv);
    k2s_agg<<<dim3(32,32,2), 256>>>(adj, adjr);
    k34_fused<<<dim3(64,4,2), 256, 73728>>>(R, Ab);
    k5_merge<<<128, 256>>>();
    k6_norm_v<<<dim3(16,32,4), 128>>>(Ab);
    k7_ar_vr<<<dim3(16,32,4), 128>>>(Ab, Arb);
    k8_out<<<dim3(64,4,2), 256>>>(Wp, out, outr);
}

// round 8
// speedup vs baseline: 1.2689x; 1.0031x over previous
#include <cuda_runtime.h>
#include <math.h>

#define BB 4
#define HH 8
#define LL 1024
#define DIMF 256
#define DH 32
#define SCL 0.0625f
#define NEGB (-1e30f)
#define VSLC (BB*LL*DIMF)

__device__ float g_xq[BB*HH*LL*DH];
__device__ float g_rk[BB*HH*LL*DH];
__device__ float g_xv[BB*HH*LL*DH];
__device__ float g_rv[BB*HH*LL*DH];
__device__ float g_q [BB*HH*LL*DH];
__device__ float g_k [BB*HH*LL*DH];
__device__ unsigned g_msk[BB*HH*LL*32];
__device__ float g_rm[BB*HH*LL];
__device__ float g_rs[BB*HH*LL];
__device__ float g_cs[BB*HH*LL];
__device__ float g_v4 [4*VSLC];
__device__ float g_vr4[4*VSLC];

/* K1: per-head projections; zero g_cs */
__global__ void k1_proj(const float* __restrict__ x, const float* __restrict__ rx,
                        const float* __restrict__ Wq, const float* __restrict__ Wk,
                        const float* __restrict__ Wv) {
    __shared__ float wq[DH*DH], wk[DH*DH], wv[DH*DH];
    __shared__ float xr[DIMF], rr[DIMF];
    int tid = threadIdx.x, bl = blockIdx.x;
    if (bl < 128) g_cs[bl*256 + tid] = 0.f;
    for (int i = tid; i < DH*DH; i += 256) { wq[i]=Wq[i]; wk[i]=Wk[i]; wv[i]=Wv[i]; }
    xr[tid] = x[(size_t)bl*DIMF + tid];
    rr[tid] = rx[(size_t)bl*DIMF + tid];
    __syncthreads();
    int h = tid>>5, d = tid&31;
    float aq=0.f, av=0.f, ak=0.f, ar=0.f;
#pragma unroll
    for (int j=0;j<DH;j++) {
        float xv_ = xr[h*DH+j], rv_ = rr[h*DH+j];
        aq += xv_*wq[j*DH+d]; av += xv_*wv[j*DH+d];
        ak += rv_*wk[j*DH+d]; ar += rv_*wv[j*DH+d];
    }
    int b = bl>>10, l = bl&1023;
    size_t o = (((size_t)b*HH + h)*LL + l)*DH + d;
    g_xq[o]=aq; g_xv[o]=av; g_rk[o]=ak; g_rv[o]=ar;
}

/* K2s: sparse aggregation (adj entries exactly {0,1}); also stores the adj
   bitmask words (z==0) so k34 never re-reads the 128MB adj tensor. */
__global__ void k2s_agg(const float* __restrict__ adj, const float* __restrict__ adjr) {
    int tid = threadIdx.x, w = tid>>5, lane = tid&31;
    int bh = blockIdx.y;
    const float* A = blockIdx.z ? adjr : adj;
    const float* X = blockIdx.z ? g_rk : g_xq;
    float*       O = blockIdx.z ? g_k  : g_q;
    const float* Ab = A + (size_t)bh*LL*LL;
    const float* Xb = X + (size_t)bh*LL*DH;
    float*       Ob = O + (size_t)bh*LL*DH;
    int lbase = blockIdx.x*32 + w*4;
    float acc[4] = {0.f,0.f,0.f,0.f};
    for (int t0=0; t0<LL; t0+=32) {
        unsigned mask[4];
#pragma unroll
        for (int r=0;r<4;r++) {
            float av = Ab[(size_t)(lbase+r)*LL + t0 + lane];
            mask[r] = __ballot_sync(0xffffffffu, av > 0.f);
        }
        if (blockIdx.z == 0) {
#pragma unroll
            for (int r=0;r<4;r++)
                if (lane == r)
                    g_msk[((size_t)bh*LL + lbase+r)*32 + (t0>>5)] = mask[r];
        }
#pragma unroll
        for (int r=0;r<4;r++) {
            unsigned m = mask[r];
            while (m) {
                int b0 = __ffs(m)-1; m &= m-1;
                float v0 = Xb[(size_t)(t0+b0)*DH + lane];
                if (m) {
                    int b1 = __ffs(m)-1; m &= m-1;
                    float v1 = Xb[(size_t)(t0+b1)*DH + lane];
                    acc[r] += v0; acc[r] += v1;
                } else acc[r] += v0;
            }
        }
    }
#pragma unroll
    for (int r=0;r<4;r++) Ob[(size_t)(lbase+r)*DH + lane] = acc[r];
}

/* K34: fused logits + leaky + R-mix + bitmask + row softmax stats.
   512 threads, 16 l-rows, full t-range (single wave: 256 blocks, 2/SM).
   Phase1: 16 warps = 8 heads x 2 l-halves, each 8l x 32t, 2x4 regs.
   Phase2: warp = (out-head, l-half), 8 rows of stats per warp. */
__global__ void __launch_bounds__(512, 2) k34_fused(const float* __restrict__ R,
                                                    float* __restrict__ Ab) {
    extern __shared__ float sm[];
    float* qs = sm;            /* [8][16][36] */
    float* ks = sm + 4608;     /* [8][32][36] */
    float* Ss = sm + 13824;    /* [8][16][36] */
    int tid = threadIdx.x, b = blockIdx.y, l0 = blockIdx.x*16;
    int w = tid>>5, lane = tid&31;
    int hh = w&7, rh = w>>3;           /* head, l-half */
    int lg = lane>>3, tg = lane&7;
    float Rr[8];
#pragma unroll
    for (int h=0;h<8;h++) Rr[h] = R[hh*8+h];
#pragma unroll
    for (int i=0;i<2;i++) {
        int e = tid + i*512;
        int h = e>>7, rem = e&127, l = rem>>3, d4 = (rem&7)*4;
        *(float4*)&qs[(h*16+l)*36+d4] =
            *(const float4*)(g_q + (((size_t)b*HH+h)*LL + l0+l)*DH + d4);
    }
    float m8[8], s8[8];
#pragma unroll
    for (int l=0;l<8;l++){ m8[l]=NEGB; s8[l]=0.f; }
    for (int t0=0; t0<LL; t0+=32) {
        __syncthreads();
#pragma unroll
        for (int i=0;i<4;i++) {
            int e = tid + i*512;
            int h = e>>8, rem = e&255, tt = rem>>3, d4 = (rem&7)*4;
            *(float4*)&ks[(h*32+tt)*36+d4] =
                *(const float4*)(g_k + (((size_t)b*HH+h)*LL + t0+tt)*DH + d4);
        }
        __syncthreads();
        {
            float s[2][4];
#pragma unroll
            for (int i=0;i<2;i++)
#pragma unroll
                for (int j=0;j<4;j++) s[i][j]=0.f;
#pragma unroll
            for (int dq=0; dq<8; dq++) {
                float4 q4[2], k4[4];
#pragma unroll
                for (int i=0;i<2;i++)
                    q4[i] = *(const float4*)&qs[(hh*16 + rh*8 + lg+4*i)*36+dq*4];
#pragma unroll
                for (int j=0;j<4;j++)
                    k4[j] = *(const float4*)&ks[(hh*32 + tg+8*j)*36+dq*4];
#pragma unroll
                for (int i=0;i<2;i++)
#pragma unroll
                    for (int j=0;j<4;j++)
                        s[i][j] += q4[i].x*k4[j].x + q4[i].y*k4[j].y
                                 + q4[i].z*k4[j].z + q4[i].w*k4[j].w;
            }
#pragma unroll
            for (int i=0;i<2;i++)
#pragma unroll
                for (int j=0;j<4;j++) {
                    float v = s[i][j]*SCL;
                    Ss[(hh*16 + rh*8 + lg+4*i)*36+tg+8*j] = v>0.f ? v : 0.01f*v;
                }
        }
        __syncthreads();
#pragma unroll
        for (int l=0;l<8;l++) {
            int lr = rh*8 + l;
            float z = 0.f;
#pragma unroll
            for (int h=0;h<8;h++) z += Rr[h]*Ss[(h*16+lr)*36 + lane];
            size_t row = ((size_t)b*HH+hh)*LL + l0+lr;
            unsigned mw = g_msk[row*32 + (t0>>5)];
            if (!((mw >> lane) & 1u)) z = NEGB;
            Ab[row*LL + t0 + lane] = z;
            float mo = m8[l];
            if (z > mo) { s8[l] = s8[l]*__expf(mo - z) + 1.f; m8[l] = z; }
            else s8[l] += __expf(z - mo);
        }
    }
#pragma unroll
    for (int l=0;l<8;l++) {
        float m = m8[l], s = s8[l];
#pragma unroll
        for (int o=16;o;o>>=1) {
            float mo = __shfl_xor_sync(0xffffffffu, m, o);
            float so = __shfl_xor_sync(0xffffffffu, s, o);
            float mn = fmaxf(m, mo);
            s = s*__expf(m-mn) + so*__expf(mo-mn);
            m = mn;
        }
        if (lane == 0) {
            size_t ridx = ((size_t)b*HH+hh)*LL + l0 + rh*8 + l;
            g_rm[ridx] = m;
            g_rs[ridx] = s;
        }
    }
}

/* K6: A = exp(z-m)/s in place; colsum += sum_l exp(A); v partial = A @ xv.
   blockIdx.z = t-chunk of 256. */
__global__ void k6_norm_v(float* __restrict__ Ab) {
    __shared__ float Ps[64][36], xs[32][36], csum[256];
    __shared__ float rm[64], ri[64];
    int tid = threadIdx.x, bh = blockIdx.y;
    int l0 = blockIdx.x * 64, tz = blockIdx.z*256;
    if (tid < 64) {
        rm[tid] = g_rm[(size_t)bh*LL + l0+tid];
        ri[tid] = 1.f / g_rs[(size_t)bh*LL + l0+tid];
    }
    csum[tid] = 0.f; csum[tid+128] = 0.f;
    int lq = tid>>3, dg = tid&7;
    float4 acc[4];
#pragma unroll
    for (int i=0;i<4;i++) acc[i] = make_float4(0.f,0.f,0.f,0.f);
    __syncthreads();
    for (int t0=tz; t0<tz+256; t0+=32) {
#pragma unroll
        for (int i=0;i<4;i++) {
            int e = tid + i*128, l = e>>3, t4 = (e&7)*4;
            float4 z = *(const float4*)(Ab + ((size_t)bh*LL + l0+l)*LL + t0 + t4);
            float m = rm[l], s = ri[l];
            float4 p;
            p.x = __expf(z.x-m)*s; p.y = __expf(z.y-m)*s;
            p.z = __expf(z.z-m)*s; p.w = __expf(z.w-m)*s;
            *(float4*)&Ps[l][t4] = p;
            *(float4*)(Ab + ((size_t)bh*LL + l0+l)*LL + t0 + t4) = p;
        }
#pragma unroll
        for (int i=0;i<2;i++) {
            int e = tid + i*128, l = e>>3, d4 = (e&7)*4;
            *(float4*)&xs[l][d4] = *(const float4*)(g_xv + ((size_t)bh*LL + t0+l)*DH + d4);
        }
        __syncthreads();
        {
            int w = tid>>5, t = tid&31;
            float s = 0.f;
#pragma unroll
            for (int r=0;r<16;r++) s += __expf(Ps[w*16+r][t]);
            atomicAdd(&csum[t0-tz+t], s);
        }
#pragma unroll
        for (int tt=0; tt<32; tt++) {
            float4 x4 = *(const float4*)&xs[tt][dg*4];
#pragma unroll
            for (int i=0;i<4;i++) {
                float p = Ps[lq+16*i][tt];
                acc[i].x += p*x4.x; acc[i].y += p*x4.y;
                acc[i].z += p*x4.z; acc[i].w += p*x4.w;
            }
        }
        __syncthreads();
    }
    int b = bh>>3, h = bh&7;
#pragma unroll
    for (int i=0;i<4;i++)
        *(float4*)(g_v4 + (size_t)blockIdx.z*VSLC
                   + (size_t)(b*LL + l0+lq+16*i)*DIMF + h*DH + dg*4) = acc[i];
    atomicAdd(&g_cs[(size_t)bh*LL + tz + tid],       csum[tid]);
    atomicAdd(&g_cs[(size_t)bh*LL + tz + tid + 128], csum[tid+128]);
}

/* K7: Ar[t,l] = exp(A[l,t])/colsum[t] (transposed write); vr partial = Ar @ rv.
   blockIdx.z = l-chunk of 256. */
__global__ void k7_ar_vr(const float* __restrict__ Ab, float* __restrict__ Ar) {
    __shared__ float Es[64][36], rs_[32][36], ci[64];
    int tid = threadIdx.x, bh = blockIdx.y;
    int t0 = blockIdx.x * 64, lz = blockIdx.z*256;
    if (tid < 64) ci[tid] = 1.f / g_cs[(size_t)bh*LL + t0 + tid];
    int tq = tid>>3, dg = tid&7;
    float4 acc[4];
#pragma unroll
    for (int i=0;i<4;i++) acc[i] = make_float4(0.f,0.f,0.f,0.f);
    __syncthreads();
    for (int l0=lz; l0<lz+256; l0+=32) {
#pragma unroll
        for (int i=0;i<4;i++) {
            int e = tid + i*128;
            int l = (e>>3)&31, t4 = (e&7)*4 + ((e>>8)<<5);
            float4 a = *(const float4*)(Ab + ((size_t)bh*LL + l0+l)*LL + t0 + t4);
            Es[t4  ][l] = __expf(a.x)*ci[t4];
            Es[t4+1][l] = __expf(a.y)*ci[t4+1];
            Es[t4+2][l] = __expf(a.z)*ci[t4+2];
            Es[t4+3][l] = __expf(a.w)*ci[t4+3];
        }
#pragma unroll
        for (int i=0;i<2;i++) {
            int e = tid + i*128, l = e>>3, d4 = (e&7)*4;
            *(float4*)&rs_[l][d4] = *(const float4*)(g_rv + ((size_t)bh*LL + l0+l)*DH + d4);
        }
        __syncthreads();
#pragma unroll
        for (int i=0;i<4;i++) {
            int e = tid + i*128, t = e>>3, l4 = (e&7)*4;
            *(float4*)(Ar + ((size_t)bh*LL + t0+t)*LL + l0 + l4) = *(float4*)&Es[t][l4];
        }
#pragma unroll
        for (int ll=0; ll<32; ll++) {
            float4 r4 = *(const float4*)&rs_[ll][dg*4];
#pragma unroll
            for (int i=0;i<4;i++) {
                float e_ = Es[tq+16*i][ll];
                acc[i].x += e_*r4.x; acc[i].y += e_*r4.y;
                acc[i].z += e_*r4.z; acc[i].w += e_*r4.w;
            }
        }
        __syncthreads();
    }
    int b = bh>>3, h = bh&7;
#pragma unroll
    for (int i=0;i<4;i++)
        *(float4*)(g_vr4 + (size_t)blockIdx.z*VSLC
                   + (size_t)(b*LL + t0+tq+16*i)*DIMF + h*DH + dg*4) = acc[i];
}

/* K8: sum 4 partial v slices, gelu, @ Wp. */
__global__ void k8_out(const float* __restrict__ Wp, float* __restrict__ out,
                       float* __restrict__ outr) {
    __shared__ float Vs[64][36], Ws[32][68];
    int tid = threadIdx.x;
    const float* V = blockIdx.z ? g_vr4 : g_v4;
    float* O = blockIdx.z ? outr : out;
    int r0 = blockIdx.x*64, n0 = blockIdx.y*64;
    int rg = tid>>4, ng = tid&15;
    float4 acc[4];
#pragma unroll
    for (int i=0;i<4;i++) acc[i] = make_float4(0.f,0.f,0.f,0.f);
    for (int k0=0; k0<DIMF; k0+=32) {
#pragma unroll
        for (int it=0; it<2; it++) {
            int e = tid + it*256;
            int r = e>>3, k4 = (e&7)*4;
            size_t off = (size_t)(r0+r)*DIMF + k0 + k4;
            float4 v0 = *(const float4*)(V + off);
            float4 v1 = *(const float4*)(V + VSLC + off);
            float4 v2 = *(const float4*)(V + 2*(size_t)VSLC + off);
            float4 v3 = *(const float4*)(V + 3*(size_t)VSLC + off);
            float4 v;
            v.x = v0.x+v1.x+v2.x+v3.x; v.y = v0.y+v1.y+v2.y+v3.y;
            v.z = v0.z+v1.z+v2.z+v3.z; v.w = v0.w+v1.w+v2.w+v3.w;
            float* pv = (float*)&v;
#pragma unroll
            for (int j=0;j<4;j++){ float xx = pv[j]; pv[j] = 0.5f*xx*(1.f+erff(xx*0.70710678f)); }
            *(float4*)&Vs[r][k4] = v;
            int kk = e>>4, n4 = (e&15)*4;
            *(float4*)&Ws[kk][n4] = *(const float4*)(Wp + (size_t)(k0+kk)*DIMF + n0 + n4);
        }
        __syncthreads();
#pragma unroll
        for (int k=0;k<32;k++) {
            float4 w4 = *(const float4*)&Ws[k][ng*4];
#pragma unroll
            for (int i=0;i<4;i++) {
                float vv = Vs[rg+16*i][k];
                acc[i].x += vv*w4.x; acc[i].y += vv*w4.y;
                acc[i].z += vv*w4.z; acc[i].w += vv*w4.w;
            }
        }
        __syncthreads();
    }
#pragma unroll
    for (int i=0;i<4;i++)
        *(float4*)(O + (size_t)(r0+rg+16*i)*DIMF + n0 + ng*4) = acc[i];
}

extern "C" void kernel_launch(void* const* d_in, const int* in_sizes, int n_in,
                              void* d_out, int out_size) {
    const float* x    = (const float*)d_in[0];
    const float* rx   = (const float*)d_in[1];
    const float* adj  = (const float*)d_in[2];
    const float* adjr = (const float*)d_in[3];
    const float* Wq   = (const float*)d_in[4];
    const float* Wk   = (const float*)d_in[5];
    const float* Wv   = (const float*)d_in[6];
    const float* R    = (const float*)d_in[7];
    const float* Wp   = (const float*)d_in[8];
    float* out  = (float*)d_out;
    float* outr = out + 1048576;
    float* Ab   = out + 2097152;
    float* Arb  = Ab + 33554432;
    static int smset = 0;
    if (!smset) {
        cudaFuncSetAttribute(k34_fused, cudaFuncAttributeMaxDynamicSharedMemorySize, 73728);
        smset = 1;
    }
    k1_proj<<<4096, 256>>>(x, rx, Wq, Wk, Wv);
    k2s_agg<<<dim3(32,32,2), 256>>>(adj, adjr);
    k34_fused<<<dim3(64,4), 512, 73728>>>(R, Ab);
    k6_norm_v<<<dim3(16,32,4), 128>>>(Ab);
    k7_ar_vr<<<dim3(16,32,4), 128>>>(Ab, Arb);
    k8_out<<<dim3(64,4,2), 256>>>(Wp, out, outr);
}